// round 2
// baseline (speedup 1.0000x reference)
#include <cuda_runtime.h>

// BalancedCELoss: loss = -sum(t==1 ? 1.6*log(p) : 0.4*log(1-p)) / N
//                 acc  = mean(round(p) == t)
// N = 16777216, pure HBM-bound reduction (128 MB read).

#define NBLK 2048
#define NTHR 256

// Deterministic two-stage reduction scratch (no cudaMalloc allowed).
__device__ float g_part_loss[NBLK];
__device__ float g_part_acc[NBLK];

__global__ void __launch_bounds__(NTHR)
bce_reduce_kernel(const float* __restrict__ inp, const int* __restrict__ tgt, int n4)
{
    const float4* __restrict__ in4 = (const float4*)inp;
    const int4*   __restrict__ tg4 = (const int4*)tgt;

    int idx    = blockIdx.x * NTHR + threadIdx.x;
    int stride = NBLK * NTHR;

    float lsum = 0.0f;
    int   cnt  = 0;

    #pragma unroll 4
    for (int i = idx; i < n4; i += stride) {
        float4 p = in4[i];
        int4   t = tg4[i];

        // weighted log term
        lsum += (t.x == 1) ? 1.6f * __logf(p.x) : 0.4f * __logf(1.0f - p.x);
        lsum += (t.y == 1) ? 1.6f * __logf(p.y) : 0.4f * __logf(1.0f - p.y);
        lsum += (t.z == 1) ? 1.6f * __logf(p.z) : 0.4f * __logf(1.0f - p.z);
        lsum += (t.w == 1) ? 1.6f * __logf(p.w) : 0.4f * __logf(1.0f - p.w);

        // round-half-to-even: 0.5 -> 0, so pred = (p > 0.5)
        cnt += ((p.x > 0.5f) == (t.x == 1));
        cnt += ((p.y > 0.5f) == (t.y == 1));
        cnt += ((p.z > 0.5f) == (t.z == 1));
        cnt += ((p.w > 0.5f) == (t.w == 1));
    }

    // warp reduce
    #pragma unroll
    for (int o = 16; o > 0; o >>= 1) {
        lsum += __shfl_down_sync(0xFFFFFFFFu, lsum, o);
        cnt  += __shfl_down_sync(0xFFFFFFFFu, cnt,  o);
    }

    __shared__ float sl[NTHR / 32];
    __shared__ int   sc[NTHR / 32];
    int warp = threadIdx.x >> 5;
    int lane = threadIdx.x & 31;
    if (lane == 0) { sl[warp] = lsum; sc[warp] = cnt; }
    __syncthreads();

    if (threadIdx.x < (NTHR / 32)) {
        lsum = sl[threadIdx.x];
        cnt  = sc[threadIdx.x];
        #pragma unroll
        for (int o = (NTHR / 64); o > 0; o >>= 1) {
            lsum += __shfl_down_sync(0xFFu, lsum, o);
            cnt  += __shfl_down_sync(0xFFu, cnt,  o);
        }
        if (threadIdx.x == 0) {
            g_part_loss[blockIdx.x] = lsum;
            g_part_acc[blockIdx.x]  = (float)cnt;
        }
    }
}

__global__ void __launch_bounds__(1024)
bce_final_kernel(float* __restrict__ out, float inv_n)
{
    int t = threadIdx.x;
    float l = g_part_loss[t] + g_part_loss[t + 1024];
    float a = g_part_acc[t]  + g_part_acc[t + 1024];

    #pragma unroll
    for (int o = 16; o > 0; o >>= 1) {
        l += __shfl_down_sync(0xFFFFFFFFu, l, o);
        a += __shfl_down_sync(0xFFFFFFFFu, a, o);
    }

    __shared__ float sl[32];
    __shared__ float sa[32];
    int warp = t >> 5;
    int lane = t & 31;
    if (lane == 0) { sl[warp] = l; sa[warp] = a; }
    __syncthreads();

    if (t < 32) {
        l = sl[t];
        a = sa[t];
        #pragma unroll
        for (int o = 16; o > 0; o >>= 1) {
            l += __shfl_down_sync(0xFFFFFFFFu, l, o);
            a += __shfl_down_sync(0xFFFFFFFFu, a, o);
        }
        if (t == 0) {
            out[0] = -l * inv_n;
            out[1] =  a * inv_n;
        }
    }
}

extern "C" void kernel_launch(void* const* d_in, const int* in_sizes, int n_in,
                              void* d_out, int out_size)
{
    const float* inp = (const float*)d_in[0];
    const int*   tgt = (const int*)d_in[1];
    float*       out = (float*)d_out;

    int n  = in_sizes[0];      // 16777216
    int n4 = n >> 2;           // float4 count (N divisible by 4)

    bce_reduce_kernel<<<NBLK, NTHR>>>(inp, tgt, n4);
    bce_final_kernel<<<1, 1024>>>(out, 1.0f / (float)n);
}

// round 4
// speedup vs baseline: 1.0106x; 1.0106x over previous
#include <cuda_runtime.h>

// BalancedCELoss: loss = -sum(t==1 ? 1.6*log(p) : 0.4*log(1-p)) / N
//                 acc  = mean(round(p) == t)
// N = 16777216; HBM-bound (128 MiB read). Single fused kernel:
// grid-stride reduce -> per-block partials -> last-block-done finalize.

#define NBLK 2048
#define NTHR 256

// Scratch (no cudaMalloc allowed). Counter self-resets -> graph-replay safe.
__device__ float        g_part_loss[NBLK];
__device__ float        g_part_acc[NBLK];
__device__ unsigned int g_done = 0;

__global__ void __launch_bounds__(NTHR)
bce_fused_kernel(const float* __restrict__ inp, const int* __restrict__ tgt,
                 float* __restrict__ out, int n4, float inv_n)
{
    const float4* __restrict__ in4 = (const float4*)inp;
    const int4*   __restrict__ tg4 = (const int4*)tgt;

    int idx    = blockIdx.x * NTHR + threadIdx.x;
    int stride = NBLK * NTHR;

    float lsum = 0.0f;
    int   cnt  = 0;

    #pragma unroll 4
    for (int i = idx; i < n4; i += stride) {
        float4 p = in4[i];
        int4   t = tg4[i];

        lsum += (t.x == 1) ? 1.6f * __logf(p.x) : 0.4f * __logf(1.0f - p.x);
        lsum += (t.y == 1) ? 1.6f * __logf(p.y) : 0.4f * __logf(1.0f - p.y);
        lsum += (t.z == 1) ? 1.6f * __logf(p.z) : 0.4f * __logf(1.0f - p.z);
        lsum += (t.w == 1) ? 1.6f * __logf(p.w) : 0.4f * __logf(1.0f - p.w);

        // round-half-to-even: 0.5 -> 0, so pred = (p > 0.5)
        cnt += ((p.x > 0.5f) == (t.x == 1));
        cnt += ((p.y > 0.5f) == (t.y == 1));
        cnt += ((p.z > 0.5f) == (t.z == 1));
        cnt += ((p.w > 0.5f) == (t.w == 1));
    }

    // warp reduce
    float asum = (float)cnt;
    #pragma unroll
    for (int o = 16; o > 0; o >>= 1) {
        lsum += __shfl_down_sync(0xFFFFFFFFu, lsum, o);
        asum += __shfl_down_sync(0xFFFFFFFFu, asum, o);
    }

    __shared__ float sl[NTHR / 32];
    __shared__ float sa[NTHR / 32];
    __shared__ bool  s_last;
    int warp = threadIdx.x >> 5;
    int lane = threadIdx.x & 31;
    if (lane == 0) { sl[warp] = lsum; sa[warp] = asum; }
    __syncthreads();

    if (threadIdx.x == 0) {
        float l = 0.0f, a = 0.0f;
        #pragma unroll
        for (int w = 0; w < NTHR / 32; w++) { l += sl[w]; a += sa[w]; }
        g_part_loss[blockIdx.x] = l;
        g_part_acc[blockIdx.x]  = a;
        __threadfence();
        unsigned int prev = atomicAdd(&g_done, 1u);
        s_last = (prev == NBLK - 1);
    }
    __syncthreads();

    if (s_last) {
        // Last block reduces the 2048 partials. Fixed order -> deterministic.
        float l = 0.0f, a = 0.0f;
        #pragma unroll
        for (int b = threadIdx.x; b < NBLK; b += NTHR) {
            l += g_part_loss[b];
            a += g_part_acc[b];
        }
        #pragma unroll
        for (int o = 16; o > 0; o >>= 1) {
            l += __shfl_down_sync(0xFFFFFFFFu, l, o);
            a += __shfl_down_sync(0xFFFFFFFFu, a, o);
        }
        if (lane == 0) { sl[warp] = l; sa[warp] = a; }
        __syncthreads();
        if (threadIdx.x == 0) {
            float lt = 0.0f, at = 0.0f;
            #pragma unroll
            for (int w = 0; w < NTHR / 32; w++) { lt += sl[w]; at += sa[w]; }
            out[0] = -lt * inv_n;
            out[1] =  at * inv_n;
            g_done = 0;   // reset for next graph replay
        }
    }
}

extern "C" void kernel_launch(void* const* d_in, const int* in_sizes, int n_in,
                              void* d_out, int out_size)
{
    const float* inp = (const float*)d_in[0];
    const int*   tgt = (const int*)d_in[1];
    float*       out = (float*)d_out;

    int n  = in_sizes[0];      // 16777216
    int n4 = n >> 2;           // float4 count (N divisible by 4)

    bce_fused_kernel<<<NBLK, NTHR>>>(inp, tgt, out, n4, 1.0f / (float)n);
}